// round 15
// baseline (speedup 1.0000x reference)
#include <cuda_runtime.h>
#include <cstdint>
#include <math.h>

#define NWIN 16
#define HN 8
#define NQ 196
#define NV 3136
#define DM 256
#define QKD 128
#define DK 16
#define DV 32
#define PE 729
#define BN_EPS 1e-5f

// attav dynamic smem (floats): P[3136] | SR[3584] | cs[256] | rb[8][3136]
#define OFF_SR 3136
#define OFF_CS 6720
#define OFF_RB 6976
#define ATT_SMEM_BYTES ((OFF_RB + 8 * 3136) * 4)   // 128256 B

// Scratch (allocation-free)
__device__ float g_qk[NWIN * DM * NQ];
__device__ float g_vv[DM * NV];
__device__ float g_A [NWIN * HN * NQ * NQ];
__device__ float g_W [NWIN * HN * NQ * DV];
__device__ float g_cag[HN * 784 * 16];
__device__ float g_pre[NV * DM];
__device__ float g_bias[HN * NQ * NQ];
__device__ int   g_pidx[NV];

// ---------------------------------------------------------------------------
// convbn tile worker: 64x64 tile, BK=16, 4x4/thread, reg-prefetch double buffer
// ---------------------------------------------------------------------------
__device__ __forceinline__ void convbn_tile(
    const float* __restrict__ xb, const float* __restrict__ w,
    const float* __restrict__ gamma, const float* __restrict__ beta,
    const float* __restrict__ mean, const float* __restrict__ var,
    float* __restrict__ ob, int P, int p0, int o0,
    float (*ws)[65], float (*xs)[64])
{
    int tid = threadIdx.x;
    int tp = tid & 15, to = tid >> 4;
    int lk = tid & 15, lr = tid >> 4;
    float acc[4][4] = {};

    float wreg[4];
    float4 xreg;
#pragma unroll
    for (int j = 0; j < 4; j++) wreg[j] = w[(o0 + lr + 16 * j) * DM + lk];
    {
        int p = p0 + 4 * lk;
        xreg = (p < P) ? *(const float4*)&xb[(size_t)lr * P + p]
                       : make_float4(0.f, 0.f, 0.f, 0.f);
    }

    for (int kk = 0; kk < DM; kk += 16) {
#pragma unroll
        for (int j = 0; j < 4; j++) ws[lk][lr + 16 * j] = wreg[j];
        *(float4*)&xs[lr][4 * lk] = xreg;
        __syncthreads();
        if (kk + 16 < DM) {
#pragma unroll
            for (int j = 0; j < 4; j++)
                wreg[j] = w[(o0 + lr + 16 * j) * DM + kk + 16 + lk];
            int p = p0 + 4 * lk;
            xreg = (p < P) ? *(const float4*)&xb[(size_t)(kk + 16 + lr) * P + p]
                           : make_float4(0.f, 0.f, 0.f, 0.f);
        }
#pragma unroll
        for (int k = 0; k < 16; k++) {
            float4 xv = *(const float4*)&xs[k][tp * 4];
#pragma unroll
            for (int j = 0; j < 4; j++) {
                float wv = ws[k][to * 4 + j];
                acc[j][0] += wv * xv.x;
                acc[j][1] += wv * xv.y;
                acc[j][2] += wv * xv.z;
                acc[j][3] += wv * xv.w;
            }
        }
        __syncthreads();
    }

    int p = p0 + tp * 4;
    if (p < P) {
#pragma unroll
        for (int j = 0; j < 4; j++) {
            int o = o0 + to * 4 + j;
            float s = gamma[o] * rsqrtf(var[o] + BN_EPS);
            float t = beta[o] - mean[o] * s;
            float4 r;
            r.x = acc[j][0] * s + t;
            r.y = acc[j][1] * s + t;
            r.z = acc[j][2] * s + t;
            r.w = acc[j][3] * s + t;
            *(float4*)&ob[(size_t)o * P + p] = r;
        }
    }
}

// ---------------------------------------------------------------------------
// fused stage-1: convbn QK | convbn V | init tables | bias gather | ca gather
// ---------------------------------------------------------------------------
__global__ void prep_kernel(const float* __restrict__ x, const float* __restrict__ v_in,
                            const float* __restrict__ ca,
                            const float* __restrict__ wqk,
                            const float* __restrict__ qk_g, const float* __restrict__ qk_b,
                            const float* __restrict__ qk_m, const float* __restrict__ qk_v,
                            const float* __restrict__ wv,
                            const float* __restrict__ v_g, const float* __restrict__ v_b2,
                            const float* __restrict__ v_m, const float* __restrict__ v_v,
                            const float* __restrict__ pe, const int* __restrict__ rel)
{
    __shared__ float ws[16][65];
    __shared__ __align__(16) float xs[16][64];
    int blk = blockIdx.x;
    int tid = threadIdx.x;

    if (blk < 256) {
        int px = blk & 3, oy = (blk >> 2) & 3, win = blk >> 4;
        convbn_tile(x + (size_t)win * DM * NQ, wqk, qk_g, qk_b, qk_m, qk_v,
                    g_qk + (size_t)win * DM * NQ, NQ, px * 64, oy * 64, ws, xs);
    } else if (blk < 452) {
        int r = blk - 256;
        int px = r % 49, oy = r / 49;
        convbn_tile(v_in, wv, v_g, v_b2, v_m, v_v, g_vv, NV, px * 64, oy * 64, ws, xs);
    } else if (blk < 465) {
        int i = (blk - 452) * 256 + tid;
        if (i < NV) {
            int khg = i / 56, kwg = i % 56;
            int mi = khg / 14, kh = khg % 14;
            int mj = kwg / 14, kw = kwg % 14;
            g_pidx[i] = (mi * 4 + mj) * 8 * 38416 + kh * 14 + kw;
        }
    } else if (blk < 1666) {
        int idx = (blk - 465) * 256 + tid;
        if (idx < HN * NQ * NQ) {
            int h = idx / (NQ * NQ);
            int r = idx % (NQ * NQ);
            g_bias[idx] = pe[h * PE + __ldg(&rel[r])];
        }
    } else {
        int idx = (blk - 1666) * 256 + tid;
        int m = idx & 15;
        int p = (idx >> 4) % 784;
        int h = idx / (784 * 16);
        int prow = p / 28, pcol = p % 28;
        int orig = (m >> 2) * 196 + (prow % 7) * 28 + (m & 3) * 7 + (pcol % 7);
        g_cag[idx] = ca[((size_t)h * 784 + p) * 784 + orig];
    }
}

// ---------------------------------------------------------------------------
// fused scores + softmax
// ---------------------------------------------------------------------------
__global__ void scores_softmax_kernel()
{
    __shared__ float qs[DK * NQ];
    __shared__ float ks[DK * NQ];
    int win = blockIdx.x, h = blockIdx.y;
    int tid = threadIdx.x;
    int warp = tid >> 5, lane = tid & 31;
    const float* qbase = g_qk + ((size_t)win * DM + h * DK) * NQ;
    const float* kbase = g_qk + ((size_t)win * DM + QKD + h * DK) * NQ;
    for (int l = tid; l < DK * NQ; l += 256) { qs[l] = qbase[l]; ks[l] = kbase[l]; }
    __syncthreads();

    float kc[7][DK];
#pragma unroll
    for (int i = 0; i < 7; i++) {
        int j = lane + 32 * i;
        bool ok = (j < NQ);
#pragma unroll
        for (int d = 0; d < DK; d++)
            kc[i][d] = ok ? ks[d * NQ + j] : 0.f;
    }

    const float* bias = g_bias + (size_t)h * NQ * NQ;
    float* Ab = g_A + ((size_t)(win * HN + h) * NQ) * NQ;

    for (int q = warp; q < NQ; q += 8) {
        float qv[DK];
#pragma unroll
        for (int d = 0; d < DK; d++) qv[d] = qs[d * NQ + q];
        float v[7];
#pragma unroll
        for (int i = 0; i < 7; i++) {
            int j = lane + 32 * i;
            float b = (j < NQ) ? __ldg(&bias[q * NQ + j]) : -1e30f;
            float s = 0.f;
#pragma unroll
            for (int d = 0; d < DK; d++) s += kc[i][d] * qv[d];
            v[i] = (j < NQ) ? (s * 0.25f + b) : -1e30f;
        }
        float m = -1e30f;
#pragma unroll
        for (int i = 0; i < 7; i++) m = fmaxf(m, v[i]);
#pragma unroll
        for (int o = 16; o; o >>= 1) m = fmaxf(m, __shfl_xor_sync(~0u, m, o));
        float sum = 0.f;
#pragma unroll
        for (int i = 0; i < 7; i++) {
            v[i] = __expf(v[i] - m);
            if (lane + 32 * i < NQ) sum += v[i];
        }
#pragma unroll
        for (int o = 16; o; o >>= 1) sum += __shfl_xor_sync(~0u, sum, o);
        float inv = __frcp_rn(sum);
#pragma unroll
        for (int i = 0; i < 7; i++) {
            int j = lane + 32 * i;
            if (j < NQ) Ab[(size_t)q * NQ + j] = v[i] * inv;
        }
    }
}

// ---------------------------------------------------------------------------
// tiny spacer so attav lands in ncu's profiled (4th) launch slot
// ---------------------------------------------------------------------------
__global__ void spacer_kernel() {}

// ---------------------------------------------------------------------------
// fused attwrite (warp-owned TMA row pipelines) + av
// ---------------------------------------------------------------------------
__device__ __forceinline__ int sb_of(int f)
{
    return (f / 196) * 224 + (f % 14) * 16;   // byte offset into SR row
}

__device__ __forceinline__ unsigned int smem_u32(const void* p)
{
    unsigned int a;
    asm("{ .reg .u64 t; cvta.to.shared.u64 t, %1; cvt.u32.u64 %0, t; }"
        : "=r"(a) : "l"(p));
    return a;
}

__global__ void __launch_bounds__(256, 1) attav_kernel(float* __restrict__ att)
{
    extern __shared__ __align__(16) float sbuf[];
    int blk = blockIdx.x;
    int tid = threadIdx.x;

    if (blk < 1568) {
        float* P  = sbuf;
        float* SR = sbuf + OFF_SR;
        float* cs = sbuf + OFF_CS;
        int qpos = blk % 196, h = blk / 196;
        int qh = qpos / 14, qw = qpos % 14;

        {
            int w = tid >> 4, m = tid & 15;
            int qi = w >> 2, qj = w & 3;
            int vh = qi * 14 + qh, vw = qj * 14 + qw;
            int p = (vh >> 1) * 28 + (vw >> 1);
            cs[tid] = g_cag[((size_t)h * 784 + p) * 16 + m];
        }
        {
            const float* arow = g_A + (size_t)h * 38416 + (size_t)qpos * 196;
            for (int vk = tid; vk < NV; vk += 256)
                P[vk] = arow[__ldg(&g_pidx[vk])];
        }
        __syncthreads();
        for (int i = tid; i < 16 * 224; i += 256) {
            int w = i / 224, r = i % 224;
            int mi = r / 56, col = r % 56;
            SR[i] = cs[w * 16 + mi * 4 + col / 14];
        }
        __syncthreads();

        // warp-owned row pipeline: warp w handles windows w and w+8
        int w = tid >> 5, lane = tid & 31;
        float* rb = sbuf + OFF_RB + w * 3136;
        unsigned int rb_u32 = smem_u32(rb);
        char* base = (char*)(att + ((size_t)h * NV + (size_t)(qh * 56 + qw)) * NV);

#pragma unroll
        for (int rr = 0; rr < 2; rr++) {
            int r = w + rr * 8;
            const char* srw = (const char*)SR + r * 896;
            // fill: 784 float4, 32 lanes -> 24.5 iterations
            for (int f = lane; f < 784; f += 32) {
                ulonglong2 pv = *(const ulonglong2*)(P + 4 * f);
                ulonglong2 sv = *(const ulonglong2*)(srw + sb_of(f));
                unsigned long long a0, a1;
                asm("mul.rn.f32x2 %0, %1, %2;" : "=l"(a0) : "l"(pv.x), "l"(sv.x));
                asm("mul.rn.f32x2 %0, %1, %2;" : "=l"(a1) : "l"(pv.y), "l"(sv.y));
                ulonglong2 res; res.x = a0; res.y = a1;
                *(ulonglong2*)(rb + 4 * f) = res;
            }
            // publish generic writes to async proxy (all lanes), then issue
            asm volatile("fence.proxy.async.shared::cta;" ::: "memory");
            __syncwarp();
            if (lane == 0) {
                long roff = (long)(r >> 2) * 9834496 + (r & 3) * 175616;
                asm volatile("cp.async.bulk.global.shared::cta.bulk_group [%0], [%1], %2;"
                             :: "l"(base + roff), "r"(rb_u32), "r"(12544)
                             : "memory");
                asm volatile("cp.async.bulk.commit_group;" ::: "memory");
                if (rr == 0)
                    asm volatile("cp.async.bulk.wait_group 0;" ::: "memory");
            }
            __syncwarp();
        }
        // drain last group before block exit (smem reuse by next block)
        if (lane == 0)
            asm volatile("cp.async.bulk.wait_group 0;" ::: "memory");
        __syncwarp();
    } else {
        float* vs = sbuf;
        int r = blk - 1568;
        int win = r & 15, h = r >> 4;
        int ki = win >> 2, kj = win & 3;
        int vbase = ki * 14 * 56 + kj * 14;
        for (int l = tid; l < NQ * DV; l += 256) {
            int d = l / NQ, kpos = l % NQ;
            int kh = kpos / 14, kw = kpos % 14;
            vs[kpos * DV + d] = g_vv[(size_t)(h * DV + d) * NV + vbase + kh * 56 + kw];
        }
        __syncthreads();
        for (int o = tid; o < NQ * DV; o += 256) {
            int q = o >> 5, d = o & 31;
            const float4* arow4 = (const float4*)(g_A + ((size_t)(win * HN + h) * NQ + q) * NQ);
            float acc = 0.f;
#pragma unroll 7
            for (int k4 = 0; k4 < NQ / 4; k4++) {
                float4 a = __ldg(&arow4[k4]);
                int k = k4 * 4;
                acc += a.x * vs[(k + 0) * DV + d];
                acc += a.y * vs[(k + 1) * DV + d];
                acc += a.z * vs[(k + 2) * DV + d];
                acc += a.w * vs[(k + 3) * DV + d];
            }
            g_W[((size_t)(win * HN + h) * NQ + q) * DV + d] = acc;
        }
    }
}

// ---------------------------------------------------------------------------
__global__ void wsum_kernel()
{
    int vq = blockIdx.x;
    int tid = threadIdx.x;
    int vh = vq / 56, vw = vq % 56;
    int qpos = (vh % 14) * 14 + (vw % 14);
    int p = (vh >> 1) * 28 + (vw >> 1);
    int h = tid >> 5, d = tid & 31;
    const float* cg = g_cag + ((size_t)h * 784 + p) * 16;
    float acc = 0.f;
#pragma unroll
    for (int m = 0; m < 16; m++)
        acc += cg[m] * g_W[((size_t)(m * HN + h) * NQ + qpos) * DV + d];
    g_pre[(size_t)vq * DM + tid] = acc;
}

// ---------------------------------------------------------------------------
// FC GEMM, 64x64/BK16/4x4, register-prefetch double buffer
// ---------------------------------------------------------------------------
__global__ void fc2_kernel(const float* __restrict__ fw, const float* __restrict__ fb,
                           float* __restrict__ out)
{
    __shared__ float ps[16][65];
    __shared__ float ws[16][65];
    int q0 = blockIdx.x * 64;
    int o0 = blockIdx.y * 64;
    int tid = threadIdx.x;
    int tq = tid & 15, to = tid >> 4;
    int lk = tid & 15, lr = tid >> 4;
    float acc[4][4] = {};

    float preg[4], wreg[4];
#pragma unroll
    for (int j = 0; j < 4; j++) {
        preg[j] = g_pre[(size_t)(q0 + lr + 16 * j) * DM + lk];
        wreg[j] = fw[(o0 + lr + 16 * j) * DM + lk];
    }

    for (int kk = 0; kk < DM; kk += 16) {
#pragma unroll
        for (int j = 0; j < 4; j++) {
            ps[lk][lr + 16 * j] = preg[j];
            ws[lk][lr + 16 * j] = wreg[j];
        }
        __syncthreads();
        if (kk + 16 < DM) {
#pragma unroll
            for (int j = 0; j < 4; j++) {
                preg[j] = g_pre[(size_t)(q0 + lr + 16 * j) * DM + kk + 16 + lk];
                wreg[j] = fw[(o0 + lr + 16 * j) * DM + kk + 16 + lk];
            }
        }
#pragma unroll
        for (int k = 0; k < 16; k++) {
            float a[4], bb[4];
#pragma unroll
            for (int i = 0; i < 4; i++) a[i] = ps[k][tq * 4 + i];
#pragma unroll
            for (int j = 0; j < 4; j++) bb[j] = ws[k][to * 4 + j];
#pragma unroll
            for (int i = 0; i < 4; i++)
#pragma unroll
                for (int j = 0; j < 4; j++)
                    acc[i][j] += a[i] * bb[j];
        }
        __syncthreads();
    }

    float4 bv = *(const float4*)&fb[o0 + to * 4];
#pragma unroll
    for (int i = 0; i < 4; i++) {
        int q = q0 + tq * 4 + i;
        float4 r;
        r.x = acc[i][0] + bv.x;
        r.y = acc[i][1] + bv.y;
        r.z = acc[i][2] + bv.z;
        r.w = acc[i][3] + bv.w;
        *(float4*)&out[(size_t)q * DM + o0 + to * 4] = r;
    }
}

// ---------------------------------------------------------------------------
extern "C" void kernel_launch(void* const* d_in, const int* in_sizes, int n_in,
                              void* d_out, int out_size)
{
    const float* x    = (const float*)d_in[0];
    const float* v_in = (const float*)d_in[1];
    const float* ca   = (const float*)d_in[2];
    const float* wqk  = (const float*)d_in[3];
    const float* qk_g = (const float*)d_in[4];
    const float* qk_b = (const float*)d_in[5];
    const float* qk_m = (const float*)d_in[6];
    const float* qk_v = (const float*)d_in[7];
    const float* wv   = (const float*)d_in[8];
    const float* v_g  = (const float*)d_in[9];
    const float* v_b  = (const float*)d_in[10];
    const float* v_m  = (const float*)d_in[11];
    const float* v_v  = (const float*)d_in[12];
    const float* fw   = (const float*)d_in[13];
    const float* fb   = (const float*)d_in[14];
    const float* pe   = (const float*)d_in[15];
    const int*   rel  = (const int*)d_in[16];
    (void)in_sizes; (void)n_in; (void)out_size;

    float* out = (float*)d_out;          // 802816 floats
    float* att = out + 802816;           // 78675968 floats

    static bool attr_done = false;
    if (!attr_done) {
        cudaFuncSetAttribute(attav_kernel,
                             cudaFuncAttributeMaxDynamicSharedMemorySize,
                             ATT_SMEM_BYTES);
        attr_done = true;
    }

    prep_kernel<<<2058, 256>>>(x, v_in, ca, wqk, qk_g, qk_b, qk_m, qk_v,
                               wv, v_g, v_b, v_m, v_v, pe, rel);
    scores_softmax_kernel<<<dim3(16, 8), 256>>>();
    spacer_kernel<<<1, 32>>>();
    attav_kernel<<<1696, 256, ATT_SMEM_BYTES>>>(att);
    wsum_kernel<<<NV, 256>>>();
    fc2_kernel<<<dim3(49, 4), 256>>>(fw, fb, out);
}

// round 16
// speedup vs baseline: 1.6862x; 1.6862x over previous
#include <cuda_runtime.h>
#include <cstdint>
#include <math.h>

#define NWIN 16
#define HN 8
#define NQ 196
#define NV 3136
#define DM 256
#define QKD 128
#define DK 16
#define DV 32
#define PE 729
#define BN_EPS 1e-5f

// Scratch (allocation-free)
__device__ float g_qk[NWIN * DM * NQ];
__device__ float g_vv[DM * NV];
__device__ float g_A [NWIN * HN * NQ * NQ];
__device__ float g_W [NWIN * HN * NQ * DV];
__device__ float g_cag[HN * 784 * 16];
__device__ float g_pre[NV * DM];
__device__ float g_bias[HN * NQ * NQ];
__device__ int   g_pidx[NV];

// ---------------------------------------------------------------------------
// convbn tile worker: 64x64 tile, BK=16, 4x4/thread, reg-prefetch double buffer
// ---------------------------------------------------------------------------
__device__ __forceinline__ void convbn_tile(
    const float* __restrict__ xb, const float* __restrict__ w,
    const float* __restrict__ gamma, const float* __restrict__ beta,
    const float* __restrict__ mean, const float* __restrict__ var,
    float* __restrict__ ob, int P, int p0, int o0,
    float (*ws)[65], float (*xs)[64])
{
    int tid = threadIdx.x;
    int tp = tid & 15, to = tid >> 4;
    int lk = tid & 15, lr = tid >> 4;
    float acc[4][4] = {};

    float wreg[4];
    float4 xreg;
#pragma unroll
    for (int j = 0; j < 4; j++) wreg[j] = w[(o0 + lr + 16 * j) * DM + lk];
    {
        int p = p0 + 4 * lk;
        xreg = (p < P) ? *(const float4*)&xb[(size_t)lr * P + p]
                       : make_float4(0.f, 0.f, 0.f, 0.f);
    }

    for (int kk = 0; kk < DM; kk += 16) {
#pragma unroll
        for (int j = 0; j < 4; j++) ws[lk][lr + 16 * j] = wreg[j];
        *(float4*)&xs[lr][4 * lk] = xreg;
        __syncthreads();
        if (kk + 16 < DM) {
#pragma unroll
            for (int j = 0; j < 4; j++)
                wreg[j] = w[(o0 + lr + 16 * j) * DM + kk + 16 + lk];
            int p = p0 + 4 * lk;
            xreg = (p < P) ? *(const float4*)&xb[(size_t)(kk + 16 + lr) * P + p]
                           : make_float4(0.f, 0.f, 0.f, 0.f);
        }
#pragma unroll
        for (int k = 0; k < 16; k++) {
            float4 xv = *(const float4*)&xs[k][tp * 4];
#pragma unroll
            for (int j = 0; j < 4; j++) {
                float wv = ws[k][to * 4 + j];
                acc[j][0] += wv * xv.x;
                acc[j][1] += wv * xv.y;
                acc[j][2] += wv * xv.z;
                acc[j][3] += wv * xv.w;
            }
        }
        __syncthreads();
    }

    int p = p0 + tp * 4;
    if (p < P) {
#pragma unroll
        for (int j = 0; j < 4; j++) {
            int o = o0 + to * 4 + j;
            float s = gamma[o] * rsqrtf(var[o] + BN_EPS);
            float t = beta[o] - mean[o] * s;
            float4 r;
            r.x = acc[j][0] * s + t;
            r.y = acc[j][1] * s + t;
            r.z = acc[j][2] * s + t;
            r.w = acc[j][3] * s + t;
            *(float4*)&ob[(size_t)o * P + p] = r;
        }
    }
}

// ---------------------------------------------------------------------------
// fused stage-1: convbn QK | convbn V | init tables | bias gather | ca gather
// ---------------------------------------------------------------------------
__global__ void prep_kernel(const float* __restrict__ x, const float* __restrict__ v_in,
                            const float* __restrict__ ca,
                            const float* __restrict__ wqk,
                            const float* __restrict__ qk_g, const float* __restrict__ qk_b,
                            const float* __restrict__ qk_m, const float* __restrict__ qk_v,
                            const float* __restrict__ wv,
                            const float* __restrict__ v_g, const float* __restrict__ v_b2,
                            const float* __restrict__ v_m, const float* __restrict__ v_v,
                            const float* __restrict__ pe, const int* __restrict__ rel)
{
    __shared__ float ws[16][65];
    __shared__ __align__(16) float xs[16][64];
    int blk = blockIdx.x;
    int tid = threadIdx.x;

    if (blk < 256) {
        int px = blk & 3, oy = (blk >> 2) & 3, win = blk >> 4;
        convbn_tile(x + (size_t)win * DM * NQ, wqk, qk_g, qk_b, qk_m, qk_v,
                    g_qk + (size_t)win * DM * NQ, NQ, px * 64, oy * 64, ws, xs);
    } else if (blk < 452) {
        int r = blk - 256;
        int px = r % 49, oy = r / 49;
        convbn_tile(v_in, wv, v_g, v_b2, v_m, v_v, g_vv, NV, px * 64, oy * 64, ws, xs);
    } else if (blk < 465) {
        int i = (blk - 452) * 256 + tid;
        if (i < NV) {
            int khg = i / 56, kwg = i % 56;
            int mi = khg / 14, kh = khg % 14;
            int mj = kwg / 14, kw = kwg % 14;
            g_pidx[i] = (mi * 4 + mj) * 8 * 38416 + kh * 14 + kw;
        }
    } else if (blk < 1666) {
        int idx = (blk - 465) * 256 + tid;
        if (idx < HN * NQ * NQ) {
            int h = idx / (NQ * NQ);
            int r = idx % (NQ * NQ);
            g_bias[idx] = pe[h * PE + __ldg(&rel[r])];
        }
    } else {
        int idx = (blk - 1666) * 256 + tid;
        int m = idx & 15;
        int p = (idx >> 4) % 784;
        int h = idx / (784 * 16);
        int prow = p / 28, pcol = p % 28;
        int orig = (m >> 2) * 196 + (prow % 7) * 28 + (m & 3) * 7 + (pcol % 7);
        g_cag[idx] = ca[((size_t)h * 784 + p) * 784 + orig];
    }
}

// ---------------------------------------------------------------------------
// fused scores + softmax + av: block (win,h) computes A[win,h] then W[win,h]
// ---------------------------------------------------------------------------
__global__ void scores_av_kernel()
{
    __shared__ float sm[2 * DK * NQ];   // qs|ks in phase 1, vs in phase 2
    float* qs = sm;
    float* ks = sm + DK * NQ;
    int win = blockIdx.x, h = blockIdx.y;
    int tid = threadIdx.x;
    int warp = tid >> 5, lane = tid & 31;
    const float* qbase = g_qk + ((size_t)win * DM + h * DK) * NQ;
    const float* kbase = g_qk + ((size_t)win * DM + QKD + h * DK) * NQ;
    for (int l = tid; l < DK * NQ; l += 256) { qs[l] = qbase[l]; ks[l] = kbase[l]; }
    __syncthreads();

    float kc[7][DK];
#pragma unroll
    for (int i = 0; i < 7; i++) {
        int j = lane + 32 * i;
        bool ok = (j < NQ);
#pragma unroll
        for (int d = 0; d < DK; d++)
            kc[i][d] = ok ? ks[d * NQ + j] : 0.f;
    }

    const float* bias = g_bias + (size_t)h * NQ * NQ;
    float* Ab = g_A + ((size_t)(win * HN + h) * NQ) * NQ;

    for (int q = warp; q < NQ; q += 8) {
        float qv[DK];
#pragma unroll
        for (int d = 0; d < DK; d++) qv[d] = qs[d * NQ + q];
        float v[7];
#pragma unroll
        for (int i = 0; i < 7; i++) {
            int j = lane + 32 * i;
            float b = (j < NQ) ? __ldg(&bias[q * NQ + j]) : -1e30f;
            float s = 0.f;
#pragma unroll
            for (int d = 0; d < DK; d++) s += kc[i][d] * qv[d];
            v[i] = (j < NQ) ? (s * 0.25f + b) : -1e30f;
        }
        float m = -1e30f;
#pragma unroll
        for (int i = 0; i < 7; i++) m = fmaxf(m, v[i]);
#pragma unroll
        for (int o = 16; o; o >>= 1) m = fmaxf(m, __shfl_xor_sync(~0u, m, o));
        float sum = 0.f;
#pragma unroll
        for (int i = 0; i < 7; i++) {
            v[i] = __expf(v[i] - m);
            if (lane + 32 * i < NQ) sum += v[i];
        }
#pragma unroll
        for (int o = 16; o; o >>= 1) sum += __shfl_xor_sync(~0u, sum, o);
        float inv = __frcp_rn(sum);
#pragma unroll
        for (int i = 0; i < 7; i++) {
            int j = lane + 32 * i;
            if (j < NQ) Ab[(size_t)q * NQ + j] = v[i] * inv;
        }
    }

    // ---- phase 2: av. syncthreads orders this block's global A writes. ----
    __syncthreads();
    float* vs = sm;   // NQ*DV = 6272 floats, reuses qs|ks exactly
    int ki = win >> 2, kj = win & 3;
    int vbase = ki * 14 * 56 + kj * 14;
    for (int l = tid; l < NQ * DV; l += 256) {
        int d = l / NQ, kpos = l % NQ;
        int kh = kpos / 14, kw = kpos % 14;
        vs[kpos * DV + d] = g_vv[(size_t)(h * DV + d) * NV + vbase + kh * 56 + kw];
    }
    __syncthreads();
    for (int o = tid; o < NQ * DV; o += 256) {
        int q = o >> 5, d = o & 31;
        const float4* arow4 = (const float4*)(Ab + (size_t)q * NQ);
        float acc = 0.f;
#pragma unroll 7
        for (int k4 = 0; k4 < NQ / 4; k4++) {
            float4 a = arow4[k4];   // plain load: own block's fresh writes
            int k = k4 * 4;
            acc += a.x * vs[(k + 0) * DV + d];
            acc += a.y * vs[(k + 1) * DV + d];
            acc += a.z * vs[(k + 2) * DV + d];
            acc += a.w * vs[(k + 3) * DV + d];
        }
        g_W[((size_t)(win * HN + h) * NQ + q) * DV + d] = acc;
    }
}

// ---------------------------------------------------------------------------
// fused attwrite (blocks 0..1567, R9-exact) + wsum (blocks 1568..4703)
// ---------------------------------------------------------------------------
__device__ __forceinline__ int sb_of(int f)
{
    return (f / 196) * 224 + (f % 14) * 16;   // byte offset into SR row
}

__global__ void attwsum_kernel(float* __restrict__ att)
{
    __shared__ __align__(16) float sbuf[6976];   // 27904 B
    int blk = blockIdx.x;
    int tid = threadIdx.x;

    if (blk < 1568) {
        float* P  = sbuf;                 // 3136
        float* SR = sbuf + 3136;          // 3584
        float* cs = sbuf + 3136 + 3584;   // 256
        int qpos = blk % 196, h = blk / 196;
        int qh = qpos / 14, qw = qpos % 14;

        {
            int w = tid >> 4, m = tid & 15;
            int qi = w >> 2, qj = w & 3;
            int vh = qi * 14 + qh, vw = qj * 14 + qw;
            int p = (vh >> 1) * 28 + (vw >> 1);
            cs[tid] = g_cag[((size_t)h * 784 + p) * 16 + m];
        }
        {
            const float* arow = g_A + (size_t)h * 38416 + (size_t)qpos * 196;
            for (int vk = tid; vk < NV; vk += 256)
                P[vk] = arow[__ldg(&g_pidx[vk])];
        }
        __syncthreads();
        for (int i = tid; i < 16 * 224; i += 256) {
            int w = i / 224, r = i % 224;
            int mi = r / 56, col = r % 56;
            SR[i] = cs[w * 16 + mi * 4 + col / 14];
        }
        __syncthreads();

        char* base = (char*)(att + ((size_t)h * NV + (size_t)(qh * 56 + qw)) * NV);

        // three interleaved f-streams
        int f0 = tid, f1 = tid + 256, f2 = tid + 512;
        ulonglong2 pv0 = *(const ulonglong2*)(P + 4 * f0);
        ulonglong2 pv1 = *(const ulonglong2*)(P + 4 * f1);
        ulonglong2 pv2 = *(const ulonglong2*)(P + 4 * f2);
        const char* sr0 = (const char*)SR + sb_of(f0);
        const char* sr1 = (const char*)SR + sb_of(f1);
        const char* sr2 = (const char*)SR + sb_of(f2);
        char* b0 = base + f0 * 16;
        char* b1 = base + f1 * 16;
        char* b2 = base + f2 * 16;

#pragma unroll
        for (int w = 0; w < 16; w++) {
            long roff = (long)(w >> 2) * 9834496 + (w & 3) * 175616;
            ulonglong2 sv0 = *(const ulonglong2*)(sr0 + w * 896);
            ulonglong2 sv1 = *(const ulonglong2*)(sr1 + w * 896);
            ulonglong2 sv2 = *(const ulonglong2*)(sr2 + w * 896);
            unsigned long long a0, a1, c0, c1, d0, d1;
            asm("mul.rn.f32x2 %0, %1, %2;" : "=l"(a0) : "l"(pv0.x), "l"(sv0.x));
            asm("mul.rn.f32x2 %0, %1, %2;" : "=l"(a1) : "l"(pv0.y), "l"(sv0.y));
            asm("mul.rn.f32x2 %0, %1, %2;" : "=l"(c0) : "l"(pv1.x), "l"(sv1.x));
            asm("mul.rn.f32x2 %0, %1, %2;" : "=l"(c1) : "l"(pv1.y), "l"(sv1.y));
            asm("mul.rn.f32x2 %0, %1, %2;" : "=l"(d0) : "l"(pv2.x), "l"(sv2.x));
            asm("mul.rn.f32x2 %0, %1, %2;" : "=l"(d1) : "l"(pv2.y), "l"(sv2.y));
            asm volatile("st.global.cs.v2.u64 [%0], {%1, %2};"
                         :: "l"(b0 + roff), "l"(a0), "l"(a1) : "memory");
            asm volatile("st.global.cs.v2.u64 [%0], {%1, %2};"
                         :: "l"(b1 + roff), "l"(c0), "l"(c1) : "memory");
            asm volatile("st.global.cs.v2.u64 [%0], {%1, %2};"
                         :: "l"(b2 + roff), "l"(d0), "l"(d1) : "memory");
        }

        // tail: f = 768..783 handled by first 16 threads
        if (tid < 16) {
            int f = tid + 768;
            ulonglong2 pv = *(const ulonglong2*)(P + 4 * f);
            const char* srb = (const char*)SR + sb_of(f);
            char* bt = base + f * 16;
#pragma unroll
            for (int w = 0; w < 16; w++) {
                long roff = (long)(w >> 2) * 9834496 + (w & 3) * 175616;
                ulonglong2 sv = *(const ulonglong2*)(srb + w * 896);
                unsigned long long a0, a1;
                asm("mul.rn.f32x2 %0, %1, %2;" : "=l"(a0) : "l"(pv.x), "l"(sv.x));
                asm("mul.rn.f32x2 %0, %1, %2;" : "=l"(a1) : "l"(pv.y), "l"(sv.y));
                asm volatile("st.global.cs.v2.u64 [%0], {%1, %2};"
                             :: "l"(bt + roff), "l"(a0), "l"(a1) : "memory");
            }
        }
    } else {
        // ---- wsum path: one block per vq ----
        int vq = blk - 1568;
        int vh = vq / 56, vw = vq % 56;
        int qpos = (vh % 14) * 14 + (vw % 14);
        int p = (vh >> 1) * 28 + (vw >> 1);
        int h = tid >> 5, d = tid & 31;
        const float* cg = g_cag + ((size_t)h * 784 + p) * 16;
        float acc = 0.f;
#pragma unroll
        for (int m = 0; m < 16; m++)
            acc += cg[m] * g_W[((size_t)(m * HN + h) * NQ + qpos) * DV + d];
        g_pre[(size_t)vq * DM + tid] = acc;
    }
}

// ---------------------------------------------------------------------------
// FC GEMM, 64x64/BK16/4x4, register-prefetch double buffer
// ---------------------------------------------------------------------------
__global__ void fc2_kernel(const float* __restrict__ fw, const float* __restrict__ fb,
                           float* __restrict__ out)
{
    __shared__ float ps[16][65];
    __shared__ float ws[16][65];
    int q0 = blockIdx.x * 64;
    int o0 = blockIdx.y * 64;
    int tid = threadIdx.x;
    int tq = tid & 15, to = tid >> 4;
    int lk = tid & 15, lr = tid >> 4;
    float acc[4][4] = {};

    float preg[4], wreg[4];
#pragma unroll
    for (int j = 0; j < 4; j++) {
        preg[j] = g_pre[(size_t)(q0 + lr + 16 * j) * DM + lk];
        wreg[j] = fw[(o0 + lr + 16 * j) * DM + lk];
    }

    for (int kk = 0; kk < DM; kk += 16) {
#pragma unroll
        for (int j = 0; j < 4; j++) {
            ps[lk][lr + 16 * j] = preg[j];
            ws[lk][lr + 16 * j] = wreg[j];
        }
        __syncthreads();
        if (kk + 16 < DM) {
#pragma unroll
            for (int j = 0; j < 4; j++) {
                preg[j] = g_pre[(size_t)(q0 + lr + 16 * j) * DM + kk + 16 + lk];
                wreg[j] = fw[(o0 + lr + 16 * j) * DM + kk + 16 + lk];
            }
        }
#pragma unroll
        for (int k = 0; k < 16; k++) {
            float a[4], bb[4];
#pragma unroll
            for (int i = 0; i < 4; i++) a[i] = ps[k][tq * 4 + i];
#pragma unroll
            for (int j = 0; j < 4; j++) bb[j] = ws[k][to * 4 + j];
#pragma unroll
            for (int i = 0; i < 4; i++)
#pragma unroll
                for (int j = 0; j < 4; j++)
                    acc[i][j] += a[i] * bb[j];
        }
        __syncthreads();
    }

    float4 bv = *(const float4*)&fb[o0 + to * 4];
#pragma unroll
    for (int i = 0; i < 4; i++) {
        int q = q0 + tq * 4 + i;
        float4 r;
        r.x = acc[i][0] + bv.x;
        r.y = acc[i][1] + bv.y;
        r.z = acc[i][2] + bv.z;
        r.w = acc[i][3] + bv.w;
        *(float4*)&out[(size_t)q * DM + o0 + to * 4] = r;
    }
}

// ---------------------------------------------------------------------------
extern "C" void kernel_launch(void* const* d_in, const int* in_sizes, int n_in,
                              void* d_out, int out_size)
{
    const float* x    = (const float*)d_in[0];
    const float* v_in = (const float*)d_in[1];
    const float* ca   = (const float*)d_in[2];
    const float* wqk  = (const float*)d_in[3];
    const float* qk_g = (const float*)d_in[4];
    const float* qk_b = (const float*)d_in[5];
    const float* qk_m = (const float*)d_in[6];
    const float* qk_v = (const float*)d_in[7];
    const float* wv   = (const float*)d_in[8];
    const float* v_g  = (const float*)d_in[9];
    const float* v_b  = (const float*)d_in[10];
    const float* v_m  = (const float*)d_in[11];
    const float* v_v  = (const float*)d_in[12];
    const float* fw   = (const float*)d_in[13];
    const float* fb   = (const float*)d_in[14];
    const float* pe   = (const float*)d_in[15];
    const int*   rel  = (const int*)d_in[16];
    (void)in_sizes; (void)n_in; (void)out_size;

    float* out = (float*)d_out;          // 802816 floats
    float* att = out + 802816;           // 78675968 floats

    prep_kernel<<<2058, 256>>>(x, v_in, ca, wqk, qk_g, qk_b, qk_m, qk_v,
                               wv, v_g, v_b, v_m, v_v, pe, rel);
    scores_av_kernel<<<dim3(16, 8), 256>>>();
    attwsum_kernel<<<1568 + NV, 256>>>(att);
    fc2_kernel<<<dim3(49, 4), 256>>>(fw, fb, out);
}